// round 2
// baseline (speedup 1.0000x reference)
#include <cuda_runtime.h>
#include <math.h>

#define N_TOK 32768
#define H_DIM 2048
#define D_DIM 256
#define K_CODE 4096

// ---- scratch (static device globals; no runtime allocation) ----
__device__ float g_z[(size_t)N_TOK * D_DIM];   // pre-projection output (N, D)
__device__ int   g_idx[N_TOK];                 // argmin code per row
__device__ float g_cnorm[K_CODE];              // ||codebook_k||^2
__device__ float g_lse;                        // logsumexp(prior_logits)
__device__ float g_loss_part[128];
__device__ float g_rate_part[128];

// ---------------- codebook squared norms ----------------
__global__ void cnorm_kernel(const float* __restrict__ cb) {
    int code = blockIdx.x * 8 + (threadIdx.x >> 5);
    int lane = threadIdx.x & 31;
    const float* row = cb + (size_t)code * D_DIM;
    float s = 0.f;
#pragma unroll
    for (int d = lane; d < D_DIM; d += 32) { float v = row[d]; s += v * v; }
#pragma unroll
    for (int o = 16; o; o >>= 1) s += __shfl_xor_sync(0xffffffffu, s, o);
    if (lane == 0) g_cnorm[code] = s;
}

// ---------------- logsumexp of prior logits ----------------
__global__ void lse_kernel(const float* __restrict__ pl) {
    __shared__ float red[1024];
    int tid = threadIdx.x;
    float m = -1e30f;
    for (int i = tid; i < K_CODE; i += 1024) m = fmaxf(m, pl[i]);
    red[tid] = m; __syncthreads();
    for (int s = 512; s; s >>= 1) { if (tid < s) red[tid] = fmaxf(red[tid], red[tid + s]); __syncthreads(); }
    m = red[0]; __syncthreads();
    float sum = 0.f;
    for (int i = tid; i < K_CODE; i += 1024) sum += expf(pl[i] - m);
    red[tid] = sum; __syncthreads();
    for (int s = 512; s; s >>= 1) { if (tid < s) red[tid] += red[tid + s]; __syncthreads(); }
    if (tid == 0) g_lse = m + logf(red[0]);
}

// ---------------- generic NT GEMM: C[M,Ncols] = Arows . B^T + bias ----------------
// A rows optionally indirected through aidx (fused codebook gather for GEMM3).
// Tiles: 128x128x16, 256 threads, 8x8 micro-tile.
__global__ __launch_bounds__(256) void gemm_nt(
    const float* __restrict__ A, const float* __restrict__ B,
    const float* __restrict__ bias, float* __restrict__ C,
    int Ncols, int Kd, const int* __restrict__ aidx)
{
    __shared__ float As[16][128];
    __shared__ float Bs[16][128];
    __shared__ int rowmap[128];
    int tid = threadIdx.x;
    int bx = blockIdx.x, by = blockIdx.y;
    if (tid < 128) {
        int rg = by * 128 + tid;
        rowmap[tid] = aidx ? aidx[rg] : rg;
    }
    __syncthreads();
    float acc[8][8] = {};
    int tx = tid & 15, ty = tid >> 4;
    int lr0 = tid >> 2;            // base row (0..63), +64 for second half
    int lk0 = (tid & 3) << 2;      // k offset within tile

    for (int k0 = 0; k0 < Kd; k0 += 16) {
#pragma unroll
        for (int h = 0; h < 2; h++) {
            int row = lr0 + h * 64;
            float4 va = *(const float4*)(A + (size_t)rowmap[row] * Kd + (k0 + lk0));
            As[lk0 + 0][row] = va.x; As[lk0 + 1][row] = va.y;
            As[lk0 + 2][row] = va.z; As[lk0 + 3][row] = va.w;
            int colg = bx * 128 + row;
            float4 vb = *(const float4*)(B + (size_t)colg * Kd + (k0 + lk0));
            Bs[lk0 + 0][row] = vb.x; Bs[lk0 + 1][row] = vb.y;
            Bs[lk0 + 2][row] = vb.z; Bs[lk0 + 3][row] = vb.w;
        }
        __syncthreads();
#pragma unroll
        for (int kk = 0; kk < 16; kk++) {
            float a[8], b[8];
            *(float4*)(a)     = *(const float4*)&As[kk][ty * 8];
            *(float4*)(a + 4) = *(const float4*)&As[kk][ty * 8 + 4];
            *(float4*)(b)     = *(const float4*)&Bs[kk][tx * 8];
            *(float4*)(b + 4) = *(const float4*)&Bs[kk][tx * 8 + 4];
#pragma unroll
            for (int i = 0; i < 8; i++)
#pragma unroll
                for (int j = 0; j < 8; j++)
                    acc[i][j] += a[i] * b[j];
        }
        __syncthreads();
    }
#pragma unroll
    for (int i = 0; i < 8; i++) {
        int rg = by * 128 + ty * 8 + i;
        float* crow = C + (size_t)rg * Ncols + bx * 128 + tx * 8;
#pragma unroll
        for (int j = 0; j < 8; j += 4) {
            int cbase = bx * 128 + tx * 8 + j;
            float4 v;
            v.x = acc[i][j + 0] + bias[cbase + 0];
            v.y = acc[i][j + 1] + bias[cbase + 1];
            v.z = acc[i][j + 2] + bias[cbase + 2];
            v.w = acc[i][j + 3] + bias[cbase + 3];
            *(float4*)(crow + j) = v;
        }
    }
}

// ---------------- fused distance GEMM + argmin ----------------
// score_k = ||c_k||^2 - 2 z.c_k  (per-row ||z||^2 constant dropped; same argmin)
__global__ __launch_bounds__(256) void dist_kernel(const float* __restrict__ cb) {
    __shared__ float As[16][128];
    __shared__ float Bs[16][128];
    __shared__ float bestv[128];
    __shared__ int   besti[128];
    int tid = threadIdx.x;
    int by = blockIdx.x;
    int tx = tid & 15, ty = tid >> 4;
    if (tid < 128) { bestv[tid] = 3.4e38f; besti[tid] = 0; }
    __syncthreads();
    int lr0 = tid >> 2;
    int lk0 = (tid & 3) << 2;

    for (int c0 = 0; c0 < K_CODE; c0 += 128) {
        float acc[8][8] = {};
        for (int k0 = 0; k0 < D_DIM; k0 += 16) {
#pragma unroll
            for (int h = 0; h < 2; h++) {
                int row = lr0 + h * 64;
                float4 va = *(const float4*)(g_z + (size_t)(by * 128 + row) * D_DIM + (k0 + lk0));
                As[lk0 + 0][row] = va.x; As[lk0 + 1][row] = va.y;
                As[lk0 + 2][row] = va.z; As[lk0 + 3][row] = va.w;
                float4 vb = *(const float4*)(cb + (size_t)(c0 + row) * D_DIM + (k0 + lk0));
                Bs[lk0 + 0][row] = vb.x; Bs[lk0 + 1][row] = vb.y;
                Bs[lk0 + 2][row] = vb.z; Bs[lk0 + 3][row] = vb.w;
            }
            __syncthreads();
#pragma unroll
            for (int kk = 0; kk < 16; kk++) {
                float a[8], b[8];
                *(float4*)(a)     = *(const float4*)&As[kk][ty * 8];
                *(float4*)(a + 4) = *(const float4*)&As[kk][ty * 8 + 4];
                *(float4*)(b)     = *(const float4*)&Bs[kk][tx * 8];
                *(float4*)(b + 4) = *(const float4*)&Bs[kk][tx * 8 + 4];
#pragma unroll
                for (int i = 0; i < 8; i++)
#pragma unroll
                    for (int j = 0; j < 8; j++)
                        acc[i][j] += a[i] * b[j];
            }
            __syncthreads();
        }
        // fused argmin over this 128-code chunk
#pragma unroll
        for (int i = 0; i < 8; i++) {
            float bv = 3.4e38f; int bi = 0x7fffffff;
#pragma unroll
            for (int j = 0; j < 8; j++) {
                int code = c0 + tx * 8 + j;
                float s = g_cnorm[code] - 2.0f * acc[i][j];
                if (s < bv || (s == bv && code < bi)) { bv = s; bi = code; }
            }
#pragma unroll
            for (int o = 8; o; o >>= 1) {   // reduce across the 16 tx lanes
                float ov = __shfl_xor_sync(0xffffffffu, bv, o);
                int   oi = __shfl_xor_sync(0xffffffffu, bi, o);
                if (ov < bv || (ov == bv && oi < bi)) { bv = ov; bi = oi; }
            }
            if (tx == 0) {
                int r = ty * 8 + i;
                if (bv < bestv[r] || (bv == bestv[r] && bi < besti[r])) {
                    bestv[r] = bv; besti[r] = bi;
                }
            }
        }
    }
    __syncthreads();
    if (tid < 128) g_idx[by * 128 + tid] = besti[tid];
}

// ---------------- vq loss + rate partials, index output ----------------
__global__ void loss_kernel(const float* __restrict__ cb, const float* __restrict__ prior,
                            float* __restrict__ out_idx, int write_idx) {
    __shared__ float redl[256];
    __shared__ float redr[256];
    int n = blockIdx.x * 256 + threadIdx.x;
    int idx = g_idx[n];
    if (write_idx) out_idx[n] = (float)idx;
    const float* zr = g_z + (size_t)n * D_DIM;
    const float* cr = cb + (size_t)idx * D_DIM;
    float s = 0.f;
#pragma unroll 8
    for (int d = 0; d < D_DIM; d += 4) {
        float4 zv = *(const float4*)(zr + d);
        float4 cv = *(const float4*)(cr + d);
        float d0 = cv.x - zv.x, d1 = cv.y - zv.y, d2 = cv.z - zv.z, d3 = cv.w - zv.w;
        s += d0 * d0 + d1 * d1 + d2 * d2 + d3 * d3;
    }
    redl[threadIdx.x] = s;
    redr[threadIdx.x] = g_lse - prior[idx];
    __syncthreads();
    for (int st = 128; st; st >>= 1) {
        if (threadIdx.x < st) {
            redl[threadIdx.x] += redl[threadIdx.x + st];
            redr[threadIdx.x] += redr[threadIdx.x + st];
        }
        __syncthreads();
    }
    if (threadIdx.x == 0) {
        g_loss_part[blockIdx.x] = redl[0];
        g_rate_part[blockIdx.x] = redr[0];
    }
}

__global__ void final_kernel(float* __restrict__ out, int write_scalars) {
    __shared__ float redl[128], redr[128];
    int t = threadIdx.x;
    redl[t] = g_loss_part[t];
    redr[t] = g_rate_part[t];
    __syncthreads();
    for (int st = 64; st; st >>= 1) {
        if (t < st) { redl[t] += redl[t + st]; redr[t] += redr[t + st]; }
        __syncthreads();
    }
    if (t == 0 && write_scalars) {
        out[0] = redr[0] / 0.69314718055994530942f;                    // rate_bits
        out[1] = 1.25f * redl[0] / (float)((size_t)N_TOK * D_DIM);     // vq_loss
    }
}

extern "C" void kernel_launch(void* const* d_in, const int* in_sizes, int n_in,
                              void* d_out, int out_size) {
    const float* embed  = (const float*)d_in[0];
    const float* pre_w  = (const float*)d_in[1];
    const float* pre_b  = (const float*)d_in[2];
    const float* cb     = (const float*)d_in[3];
    const float* post_w = (const float*)d_in[4];
    const float* post_b = (const float*)d_in[5];
    const float* prior  = (const float*)d_in[6];
    float* out = (float*)d_out;

    float* zptr; cudaGetSymbolAddress((void**)&zptr, g_z);
    int*   iptr; cudaGetSymbolAddress((void**)&iptr, g_idx);

    cnorm_kernel<<<K_CODE / 8, 256>>>(cb);
    lse_kernel<<<1, 1024>>>(prior);

    // z = embed @ pre_w^T + pre_b      (M=N_TOK, Ncols=D, K=H)
    gemm_nt<<<dim3(D_DIM / 128, N_TOK / 128), 256>>>(embed, pre_w, pre_b, zptr, D_DIM, H_DIM, nullptr);

    // nearest codebook index per row (fused distance GEMM + argmin)
    dist_kernel<<<N_TOK / 128, 256>>>(cb);

    // embed_hat = codebook[idx] @ post_w^T + post_b   (M=N_TOK, Ncols=H, K=D)
    gemm_nt<<<dim3(H_DIM / 128, N_TOK / 128), 256>>>(cb, post_w, post_b, out, H_DIM, D_DIM, iptr);

    long long need = (long long)N_TOK * H_DIM + N_TOK + 2;
    int full = ((long long)out_size >= need) ? 1 : 0;
    loss_kernel<<<128, 256>>>(cb, prior, out + (size_t)N_TOK * H_DIM, full);
    final_kernel<<<1, 128>>>(out + (size_t)N_TOK * H_DIM + N_TOK, full);
}